// round 1
// baseline (speedup 1.0000x reference)
#include <cuda_runtime.h>
#include <cstdint>

// ---------------------------------------------------------------------------
// GlobalFusion: sparse->dense scatter fusion, DIM=96, C=24.
// Outputs (f32, concatenated in tuple order):
//   updated_mask   [96^3]            off 0
//   current_volume [96^3 * 24]       off 884736
//   global_volume  [96^3 * 24]       off 22118400
//   target_volume  [96^3]            off 43352064
//   valid          [300000]          off 44236800
//   valid_target   [200000]          off 44536800
//   near_mask      [300000]          off 44736800
// total = 45036800
// ---------------------------------------------------------------------------

#define DIMV   96
#define NCELLS (96 * 96 * 96)   // 884736
#define CCH    24
#define NC4    6                // 24 floats = 6 float4
#define N_CUR  150000
#define N_GLB  300000
#define N_TGT  100000
#define N_GTGT 200000

#define OFF_UPD 0
#define OFF_CV  884736
#define OFF_GV  22118400
#define OFF_TV  43352064
#define OFF_VAL 44236800
#define OFF_VT  44536800
#define OFF_NR  44736800

// Scratch (no device allocation allowed; static __device__ globals instead)
__device__ int           g_cur_win[NCELLS];
__device__ int           g_glb_win[NCELLS];
__device__ int           g_tgt_win[NCELLS];
__device__ unsigned char g_valid_vol[NCELLS];
__device__ unsigned char g_occ[NCELLS];

// ---------------------------------------------------------------------------
// 1) reset scratch
// ---------------------------------------------------------------------------
__global__ void k_init()
{
    int i = blockIdx.x * blockDim.x + threadIdx.x;
    if (i < NCELLS) {
        g_cur_win[i]   = -1;
        g_glb_win[i]   = -1;
        g_tgt_win[i]   = -1;
        g_valid_vol[i] = 0;
        g_occ[i]       = 0;
    }
}

// ---------------------------------------------------------------------------
// 2) current-fragment scatter: visibility flags, occupancy flags, value winner
//    (last duplicate row wins in JAX CPU scatter -> atomicMax on row index)
// ---------------------------------------------------------------------------
__global__ void k_cur(const int* __restrict__ cc,
                      const int* __restrict__ grid_mask,
                      const int* __restrict__ occupancy)
{
    int i = blockIdx.x * blockDim.x + threadIdx.x;
    if (i >= N_CUR) return;
    int x = cc[3 * i + 0];
    int y = cc[3 * i + 1];
    int z = cc[3 * i + 2];
    int cell = (x * DIMV + y) * DIMV + z;
    if (grid_mask[i]) g_valid_vol[cell] = 1;
    if (occupancy[i]) g_occ[cell] = 1;
    atomicMax(&g_cur_win[cell], i);
}

// ---------------------------------------------------------------------------
// 3) target scatter (fused): rows [0, N_GTGT) = global target (priority i,
//    scattered first); rows [N_GTGT, N_GTGT+N_TGT) = current-fragment target
//    (priority N_GTGT + j, scattered second -> always wins over global).
// ---------------------------------------------------------------------------
__global__ void k_tgt(const int* __restrict__ gct,     // global_coords_target
                      const int* __restrict__ ct,      // coords_target_global
                      const int* __restrict__ org,
                      float* __restrict__ out_vt)      // valid_target
{
    int i = blockIdx.x * blockDim.x + threadIdx.x;
    if (i >= N_GTGT + N_TGT) return;

    if (i < N_GTGT) {
        int ox = __ldg(&org[0]), oy = __ldg(&org[1]), oz = __ldg(&org[2]);
        int x = gct[3 * i + 0] - ox;
        int y = gct[3 * i + 1] - oy;
        int z = gct[3 * i + 2] - oz;
        bool inb = ((unsigned)x < DIMV) && ((unsigned)y < DIMV) && ((unsigned)z < DIMV);
        out_vt[i] = inb ? 1.0f : 0.0f;
        if (inb) {
            int cell = (x * DIMV + y) * DIMV + z;
            atomicMax(&g_tgt_win[cell], i);
        }
    } else {
        int j = i - N_GTGT;
        int x = ct[3 * j + 0];
        int y = ct[3 * j + 1];
        int z = ct[3 * j + 2];
        int cell = (x * DIMV + y) * DIMV + z;
        atomicMax(&g_tgt_win[cell], N_GTGT + j);
    }
}

// ---------------------------------------------------------------------------
// 4) global-fragment rows: in-bounds + visibility gather, emit valid/near,
//    winner for global_volume. Must run after k_cur (reads g_valid_vol).
// ---------------------------------------------------------------------------
__global__ void k_glb(const int* __restrict__ gc,
                      const int* __restrict__ org,
                      float* __restrict__ out_valid,
                      float* __restrict__ out_near)
{
    int i = blockIdx.x * blockDim.x + threadIdx.x;
    if (i >= N_GLB) return;
    int ox = __ldg(&org[0]), oy = __ldg(&org[1]), oz = __ldg(&org[2]);
    int x = gc[3 * i + 0] - ox;
    int y = gc[3 * i + 1] - oy;
    int z = gc[3 * i + 2] - oz;
    bool inb = ((unsigned)x < DIMV) && ((unsigned)y < DIMV) && ((unsigned)z < DIMV);
    bool valid = false;
    if (inb) {
        int cell = (x * DIMV + y) * DIMV + z;
        valid = (g_valid_vol[cell] != 0);
        if (valid) atomicMax(&g_glb_win[cell], i);
    }
    out_valid[i] = valid ? 1.0f : 0.0f;
    out_near[i]  = (inb && !valid) ? 1.0f : 0.0f;
}

// ---------------------------------------------------------------------------
// 5) resolve: one thread per float4 slot (NCELLS * 6). Writes the full
//    current_volume and global_volume exactly once (zeros where no winner),
//    fully coalesced stores. q==0 lane also emits updated_mask + target.
// ---------------------------------------------------------------------------
__global__ void k_resolve(const float4* __restrict__ cur_vals,   // [N_CUR*6]
                          const float4* __restrict__ glb_vals,   // [N_GLB*6]
                          const float*  __restrict__ g_tsdf,     // [N_GTGT]
                          const float*  __restrict__ c_tsdf,     // [N_TGT]
                          float* __restrict__ out)
{
    int tid = blockIdx.x * blockDim.x + threadIdx.x;
    if (tid >= NCELLS * NC4) return;
    int cell = tid / NC4;
    int q    = tid - cell * NC4;

    float4 zero = make_float4(0.f, 0.f, 0.f, 0.f);

    int wc = g_cur_win[cell];
    float4 cv = (wc >= 0) ? __ldg(&cur_vals[wc * NC4 + q]) : zero;
    reinterpret_cast<float4*>(out + OFF_CV)[tid] = cv;

    int wg = g_glb_win[cell];
    float4 gv = (wg >= 0) ? __ldg(&glb_vals[wg * NC4 + q]) : zero;
    reinterpret_cast<float4*>(out + OFF_GV)[tid] = gv;

    if (q == 0) {
        out[OFF_UPD + cell] = (wg >= 0 || g_occ[cell]) ? 1.0f : 0.0f;
        int wt = g_tgt_win[cell];
        float tv = 1.0f;
        if (wt >= 0)
            tv = (wt < N_GTGT) ? __ldg(&g_tsdf[wt]) : __ldg(&c_tsdf[wt - N_GTGT]);
        out[OFF_TV + cell] = tv;
    }
}

// ---------------------------------------------------------------------------
extern "C" void kernel_launch(void* const* d_in, const int* in_sizes, int n_in,
                              void* d_out, int out_size)
{
    const int*   current_coords     = (const int*)  d_in[0];
    const float* current_values     = (const float*)d_in[1];
    const int*   global_coords      = (const int*)  d_in[2];
    const float* global_value       = (const float*)d_in[3];
    const int*   coords_tgt_global  = (const int*)  d_in[4];   // current-frame target coords
    const float* tsdf_target        = (const float*)d_in[5];
    const int*   global_coords_tgt  = (const int*)  d_in[6];
    const float* global_tsdf_target = (const float*)d_in[7];
    const int*   relative_origin    = (const int*)  d_in[8];
    const int*   grid_mask          = (const int*)  d_in[9];
    const int*   occupancy          = (const int*)  d_in[10];

    float* out = (float*)d_out;

    const int B = 256;
    k_init<<<(NCELLS + B - 1) / B, B>>>();
    k_cur<<<(N_CUR + B - 1) / B, B>>>(current_coords, grid_mask, occupancy);
    k_tgt<<<(N_GTGT + N_TGT + B - 1) / B, B>>>(global_coords_tgt, coords_tgt_global,
                                               relative_origin, out + OFF_VT);
    k_glb<<<(N_GLB + B - 1) / B, B>>>(global_coords, relative_origin,
                                      out + OFF_VAL, out + OFF_NR);
    k_resolve<<<(NCELLS * NC4 + B - 1) / B, B>>>(
        (const float4*)current_values, (const float4*)global_value,
        global_tsdf_target, tsdf_target, out);
}